// round 3
// baseline (speedup 1.0000x reference)
#include <cuda_runtime.h>
#include <math.h>

// Problem: y[t][c] = x[t][c] + beta * y[t-1][c], beta = sigmoid(beta_param)
//   T = 1024, C = B*D = 16384 columns, fp32.
#define T_DIM   1024
#define C_DIM   16384
#define SEG     32                  // segments along T
#define L_DIM   (T_DIM/SEG)         // 32 rows per segment
#define TPB     256                 // threads per block = columns per block
#define NCB     (C_DIM/TPB)         // 64 column-blocks
#define NBLK    (SEG*NCB)           // 2048 blocks

__device__ float          g_agg[SEG * C_DIM];   // per-(segment, column) aggregates
__device__ volatile int   g_flag[NBLK];
__device__ unsigned int   g_ticket;

__global__ void pli_init_kernel() {
    int i = blockIdx.x * blockDim.x + threadIdx.x;
    if (i < NBLK) g_flag[i] = 0;
    if (i == 0)  g_ticket = 0u;
}

__global__ __launch_bounds__(TPB)
void pli_scan_kernel(const float* __restrict__ x,
                     const float* __restrict__ beta_param,
                     float* __restrict__ y) {
    __shared__ float tile[L_DIM * TPB];          // 32 KB: rows x 256 cols
    __shared__ unsigned int s_vbid;

    // Ticket: segment-major issue order guarantees predecessors are resident.
    if (threadIdx.x == 0) s_vbid = atomicAdd(&g_ticket, 1u);
    __syncthreads();
    const unsigned int vbid = s_vbid;
    const int seg  = (int)(vbid / NCB);
    const int cb   = (int)(vbid % NCB);
    const int tid  = threadIdx.x;
    const int col  = cb * TPB + tid;
    const int t0   = seg * L_DIM;

    const float beta = 1.0f / (1.0f + expf(-__ldg(beta_param)));

    // ---- vectorized tile load: 8 x LDG.128 per thread, front-batched ----
    // tile is L_DIM x TPB floats = (L_DIM*TPB/4) float4s; row holds TPB/4 float4s.
    {
        const float4* xb = (const float4*)(x + (size_t)t0 * C_DIM + (size_t)cb * TPB);
        float4* tb = (float4*)tile;
        const size_t row_f4 = C_DIM / 4;         // float4 stride between rows in gmem
#pragma unroll
        for (int j = 0; j < (L_DIM * TPB / 4) / TPB; ++j) {
            int f = tid + j * TPB;               // flat float4 index in tile
            int r = f / (TPB / 4);
            int c = f % (TPB / 4);
            tb[f] = xb[(size_t)r * row_f4 + c];
        }
    }
    __syncthreads();

    // ---- local inclusive scan over smem column, WRITING RESULTS BACK ----
    float acc = tile[tid];
#pragma unroll
    for (int k = 1; k < L_DIM; ++k) {
        acc = fmaf(beta, acc, tile[k * TPB + tid]);
        tile[k * TPB + tid] = acc;               // store inclusive prefix
    }

    // ---- publish aggregate (release) ----
    g_agg[seg * C_DIM + col] = acc;
    __threadfence();
    __syncthreads();
    if (tid == 0) g_flag[vbid] = 1;

    // beta^L via repeated squaring (L = 32 = 2^5)
    float betaL = beta;
#pragma unroll
    for (int i = 0; i < 5; ++i) betaL *= betaL;

    // ---- truncated decoupled lookback ----
    // P = y[t0-1] = sum_{j>=1} betaL^{j-1} * agg[seg-j]; stop when weight negligible.
    float P = 0.0f;
    {
        float w = 1.0f;
        for (int s = seg - 1; s >= 0 && w > 3e-13f; --s) {
            if (tid == 0) {
                while (g_flag[s * NCB + cb] == 0) { __nanosleep(40); }
            }
            __syncthreads();
            __threadfence();                     // acquire
            P = fmaf(w, g_agg[s * C_DIM + col], P);
            w *= betaL;
        }
    }

    // ---- final: y[t0+k] = scanned[k] + beta^{k+1} * P ----
    float* yp = y + (size_t)t0 * C_DIM + col;
    float f = beta;
#pragma unroll
    for (int k = 0; k < L_DIM; ++k) {
        yp[(size_t)k * C_DIM] = fmaf(f, P, tile[k * TPB + tid]);
        f *= beta;
    }
}

extern "C" void kernel_launch(void* const* d_in, const int* in_sizes, int n_in,
                              void* d_out, int out_size) {
    const float* x  = (const float*)d_in[0];
    const float* bp = (const float*)d_in[1];
    float*       y  = (float*)d_out;
    (void)in_sizes; (void)n_in; (void)out_size;

    pli_init_kernel<<<(NBLK + 255) / 256, 256>>>();
    pli_scan_kernel<<<NBLK, TPB>>>(x, bp, y);
}

// round 10
// speedup vs baseline: 1.6641x; 1.6641x over previous
#include <cuda_runtime.h>
#include <math.h>

// y[t][c] = x[t][c] + beta * y[t-1][c],  beta = sigmoid(beta_param)
// T = 1024 rows, C = 16384 columns, fp32.
//
// Halo formulation: beta^k decays fast (beta = sigmoid(2) ~ 0.881 =>
// beta^147 < 1e-8), so each 128-row segment computes its incoming state
// y[t0-1] directly from at most ~147 preceding x rows. No inter-block sync.
#define T_DIM   1024
#define C_DIM   16384
#define L_DIM   128            // rows per block (segment length)
#define TPB     256            // threads per block = columns per block
#define NCB     (C_DIM/TPB)    // 64 column-blocks
#define NSEG    (T_DIM/L_DIM)  // 8 segments

__global__ __launch_bounds__(TPB)
void pli_halo_kernel(const float* __restrict__ x,
                     const float* __restrict__ beta_param,
                     float* __restrict__ y) {
    const int col = blockIdx.x * TPB + threadIdx.x;
    const int t0  = blockIdx.y * L_DIM;

    const float beta = 1.0f / (1.0f + expf(-__ldg(beta_param)));

    // Halo length: smallest k with beta^k < 1e-8, i.e. k > 18.42/(-ln beta).
    // (R6/R8 bug: a stray minus sign made this negative -> halo skipped.)
    const float logb = logf(beta);
    int kneed = (logb < -1e-7f) ? (int)(18.4207f / (-logb)) + 2 : T_DIM;
    if (kneed < 0) kneed = 0;
    const int jmax = (t0 < kneed) ? t0 : kneed;

    const float*  xp = x + (size_t)t0 * C_DIM + col;
    float*        yp = y + (size_t)t0 * C_DIM + col;
    const ptrdiff_t Cs = C_DIM;

    const float b4 = (beta * beta) * (beta * beta);

    // ---- halo pass: P = y[t0-1] = sum_{j=1..jmax} beta^(j-1) * x[t0-j] ----
    float P = 0.0f;
    {
        float w = 1.0f;            // beta^(j-1) at loop head
        int j = 1;
        for (; j + 3 <= jmax; j += 4) {
            float a0 = xp[-(ptrdiff_t)(j + 0) * Cs];
            float a1 = xp[-(ptrdiff_t)(j + 1) * Cs];
            float a2 = xp[-(ptrdiff_t)(j + 2) * Cs];
            float a3 = xp[-(ptrdiff_t)(j + 3) * Cs];
            // inner = a0 + beta*a1 + beta^2*a2 + beta^3*a3
            float inner = fmaf(beta, fmaf(beta, fmaf(beta, a3, a2), a1), a0);
            P = fmaf(w, inner, P);
            w *= b4;
        }
        for (; j <= jmax; ++j) {
            P = fmaf(w, xp[-(ptrdiff_t)j * Cs], P);
            w *= beta;
        }
    }

    // ---- streaming scan: acc = y[t0-1], y[t0+k] = x[t0+k] + beta*acc ----
    float acc = P;
#pragma unroll
    for (int kk = 0; kk < L_DIM; kk += 8) {
        float v0 = xp[(ptrdiff_t)(kk + 0) * Cs];
        float v1 = xp[(ptrdiff_t)(kk + 1) * Cs];
        float v2 = xp[(ptrdiff_t)(kk + 2) * Cs];
        float v3 = xp[(ptrdiff_t)(kk + 3) * Cs];
        float v4 = xp[(ptrdiff_t)(kk + 4) * Cs];
        float v5 = xp[(ptrdiff_t)(kk + 5) * Cs];
        float v6 = xp[(ptrdiff_t)(kk + 6) * Cs];
        float v7 = xp[(ptrdiff_t)(kk + 7) * Cs];
        acc = fmaf(beta, acc, v0); yp[(ptrdiff_t)(kk + 0) * Cs] = acc;
        acc = fmaf(beta, acc, v1); yp[(ptrdiff_t)(kk + 1) * Cs] = acc;
        acc = fmaf(beta, acc, v2); yp[(ptrdiff_t)(kk + 2) * Cs] = acc;
        acc = fmaf(beta, acc, v3); yp[(ptrdiff_t)(kk + 3) * Cs] = acc;
        acc = fmaf(beta, acc, v4); yp[(ptrdiff_t)(kk + 4) * Cs] = acc;
        acc = fmaf(beta, acc, v5); yp[(ptrdiff_t)(kk + 5) * Cs] = acc;
        acc = fmaf(beta, acc, v6); yp[(ptrdiff_t)(kk + 6) * Cs] = acc;
        acc = fmaf(beta, acc, v7); yp[(ptrdiff_t)(kk + 7) * Cs] = acc;
    }
}

extern "C" void kernel_launch(void* const* d_in, const int* in_sizes, int n_in,
                              void* d_out, int out_size) {
    const float* x  = (const float*)d_in[0];
    const float* bp = (const float*)d_in[1];
    float*       y  = (float*)d_out;
    (void)in_sizes; (void)n_in; (void)out_size;

    dim3 grid(NCB, NSEG);
    pli_halo_kernel<<<grid, TPB>>>(x, bp, y);
}